// round 2
// baseline (speedup 1.0000x reference)
#include <cuda_runtime.h>
#include <cstdint>
#include <cstdio>

#define NN_ 4096
#define FIN_ 512
#define HID_ 256
#define NE_MAX 131072

// ---------------- scratch (no allocs allowed) ----------------
__device__ float g_h[NN_ * HID_];
__device__ float g_z0[NN_ * HID_];
__device__ float g_bufA[NN_ * HID_];
__device__ float g_t1[NN_ * HID_];
__device__ float g_t2[NN_ * HID_];
__device__ float g_u1[NN_ * HID_];
__device__ float g_sig[(size_t)NN_ * NN_];

__device__ int   g_cnt[NN_];
__device__ int   g_ptrR[NN_ + 1];
__device__ int   g_nextR[NN_];
__device__ int   g_colR[NE_MAX];
__device__ float g_valR[NE_MAX];
__device__ int   g_ptrC[NN_ + 1];
__device__ int   g_nextC[NN_];
__device__ int   g_colC[NE_MAX];
__device__ float g_valC[NE_MAX];

// ---------------- CSR build ----------------
__global__ void zero_int_kernel(int* p, int n) {
    int i = blockIdx.x * blockDim.x + threadIdx.x;
    if (i < n) p[i] = 0;
}

__global__ void hist_kernel(const int* __restrict__ keys, int* __restrict__ cnt, int ne) {
    int i = blockIdx.x * blockDim.x + threadIdx.x;
    if (i < ne) atomicAdd(&cnt[keys[i]], 1);
}

// single block, 1024 threads, 4 elements each -> exclusive scan of 4096 counts
__global__ void exscan_kernel(const int* __restrict__ cnt, int* __restrict__ rowptr,
                              int* __restrict__ nxt) {
    __shared__ int sums[1024];
    int t = threadIdx.x;
    int v0 = cnt[t * 4 + 0], v1 = cnt[t * 4 + 1], v2 = cnt[t * 4 + 2], v3 = cnt[t * 4 + 3];
    int tot = v0 + v1 + v2 + v3;
    sums[t] = tot;
    __syncthreads();
    for (int off = 1; off < 1024; off <<= 1) {
        int x = (t >= off) ? sums[t - off] : 0;
        __syncthreads();
        sums[t] += x;
        __syncthreads();
    }
    int run = (t > 0) ? sums[t - 1] : 0;
    rowptr[t * 4 + 0] = run; nxt[t * 4 + 0] = run; run += v0;
    rowptr[t * 4 + 1] = run; nxt[t * 4 + 1] = run; run += v1;
    rowptr[t * 4 + 2] = run; nxt[t * 4 + 2] = run; run += v2;
    rowptr[t * 4 + 3] = run; nxt[t * 4 + 3] = run; run += v3;
    if (t == 1023) rowptr[4096] = run;
}

__global__ void scatter_kernel(const int* __restrict__ keys, const int* __restrict__ other,
                               const float* __restrict__ vals, int* __restrict__ nxt,
                               int* __restrict__ ecol, float* __restrict__ eval, int ne) {
    int i = blockIdx.x * blockDim.x + threadIdx.x;
    if (i < ne) {
        int pos = atomicAdd(&nxt[keys[i]], 1);
        ecol[pos] = other[i];
        eval[pos] = vals[i];
    }
}

// ---------------- SpMM (CSR): out[r,:] = sum_e val[e] * in[col[e],:] ----------------
__global__ __launch_bounds__(HID_) void spmm_csr_kernel(
    const int* __restrict__ rowptr, const int* __restrict__ ecol,
    const float* __restrict__ eval, const float* __restrict__ in,
    float* __restrict__ out, int do_relu) {
    int r = blockIdx.x;
    int f = threadIdx.x;
    int s = rowptr[r], e = rowptr[r + 1];
    __shared__ int   scol[HID_];
    __shared__ float sval[HID_];
    float acc = 0.f;
    for (int base = s; base < e; base += HID_) {
        int n = e - base;
        if (n > HID_) n = HID_;
        if (f < n) { scol[f] = ecol[base + f]; sval[f] = eval[base + f]; }
        __syncthreads();
        #pragma unroll 4
        for (int i = 0; i < n; i++) {
            acc += sval[i] * in[scol[i] * HID_ + f];
        }
        __syncthreads();
    }
    out[r * HID_ + f] = do_relu ? fmaxf(acc, 0.f) : acc;
}

// ---------------- GEMM: C[M,Nc] = epi(A[M,K] @ B + D) ----------------
// TRB=false: B is [K,Nc] row-major. TRB=true: B is [Nc,K] row-major (i.e. A@B^T).
// EPI: 0 none, 1 relu, 2 sigmoid, 3 add D then relu.
template <bool TRB, int EPI>
__global__ __launch_bounds__(256) void gemm64_kernel(
    const float* __restrict__ A, const float* __restrict__ B,
    const float* __restrict__ D, float* __restrict__ C,
    int M, int Nc, int K) {
    const int BM = 64, BN = 64, BK = 16;
    __shared__ float As[BK][BM + 4];
    __shared__ float Bs[BK][BN + 4];
    int tid = threadIdx.x;
    int m0 = blockIdx.y * BM;
    int n0 = blockIdx.x * BN;
    int tx = tid & 15;   // n sub-tile
    int ty = tid >> 4;   // m sub-tile
    int lr = tid >> 2;   // 0..63 (row within tile for loads)
    int lq = tid & 3;    // 0..3  (float4 index within 16-wide k slab)
    float acc[4][4] = {};

    for (int k0 = 0; k0 < K; k0 += BK) {
        // A tile (transposed into smem)
        {
            const float4 v = *reinterpret_cast<const float4*>(
                &A[(size_t)(m0 + lr) * K + k0 + lq * 4]);
            As[lq * 4 + 0][lr] = v.x;
            As[lq * 4 + 1][lr] = v.y;
            As[lq * 4 + 2][lr] = v.z;
            As[lq * 4 + 3][lr] = v.w;
        }
        if (!TRB) {
            int j = tid >> 4, q = tid & 15;
            const float4 v = *reinterpret_cast<const float4*>(
                &B[(size_t)(k0 + j) * Nc + n0 + q * 4]);
            *reinterpret_cast<float4*>(&Bs[j][q * 4]) = v;
        } else {
            const float4 v = *reinterpret_cast<const float4*>(
                &B[(size_t)(n0 + lr) * K + k0 + lq * 4]);
            Bs[lq * 4 + 0][lr] = v.x;
            Bs[lq * 4 + 1][lr] = v.y;
            Bs[lq * 4 + 2][lr] = v.z;
            Bs[lq * 4 + 3][lr] = v.w;
        }
        __syncthreads();
        #pragma unroll
        for (int k = 0; k < BK; k++) {
            float a[4], b[4];
            #pragma unroll
            for (int i = 0; i < 4; i++) a[i] = As[k][ty * 4 + i];
            #pragma unroll
            for (int j = 0; j < 4; j++) b[j] = Bs[k][tx * 4 + j];
            #pragma unroll
            for (int i = 0; i < 4; i++)
                #pragma unroll
                for (int j = 0; j < 4; j++)
                    acc[i][j] += a[i] * b[j];
        }
        __syncthreads();
    }

    #pragma unroll
    for (int i = 0; i < 4; i++) {
        int m = m0 + ty * 4 + i;
        #pragma unroll
        for (int j = 0; j < 4; j++) {
            int n = n0 + tx * 4 + j;
            size_t idx = (size_t)m * Nc + n;
            float v = acc[i][j];
            if (EPI == 1) v = fmaxf(v, 0.f);
            else if (EPI == 2) v = 1.f / (1.f + __expf(-v));
            else if (EPI == 3) v = fmaxf(v + D[idx], 0.f);
            C[idx] = v;
        }
    }
}

// ---------------- prediction head: log_softmax([z_iv|z_c] @ linW + b) ----------------
__global__ void pred_kernel(const float* __restrict__ z_iv, const float* __restrict__ z_c,
                            const float* __restrict__ linW, const float* __restrict__ linb,
                            float* __restrict__ out) {
    int i = blockIdx.x * blockDim.x + threadIdx.x;
    if (i >= NN_) return;
    float l0 = linb[0], l1 = linb[1];
    #pragma unroll 4
    for (int k = 0; k < HID_; k++) {
        float v = z_iv[i * HID_ + k];
        l0 += v * linW[k * 2 + 0];
        l1 += v * linW[k * 2 + 1];
    }
    #pragma unroll 4
    for (int k = 0; k < HID_; k++) {
        float v = z_c[i * HID_ + k];
        l0 += v * linW[(HID_ + k) * 2 + 0];
        l1 += v * linW[(HID_ + k) * 2 + 1];
    }
    float m = fmaxf(l0, l1);
    float lse = m + logf(expf(l0 - m) + expf(l1 - m));
    out[i * 2 + 0] = l0 - lse;
    out[i * 2 + 1] = l1 - lse;
}

__global__ void write_loss_kernel(float* p) { *p = 0.f; }

// ---------------- host ----------------
static void* sym(const void* s) {
    void* p = nullptr;
    cudaGetSymbolAddress(&p, s);
    return p;
}

extern "C" void kernel_launch(void* const* d_in, const int* in_sizes, int n_in,
                              void* d_out, int out_size) {
    const float* X     = (const float*)d_in[0];
    const int*   arows = (const int*)d_in[1];
    const int*   acols = (const int*)d_in[2];
    const float* avals = (const float*)d_in[3];
    const float* Wsh   = (const float*)d_in[4];
    const float* Wb[3] = {(const float*)d_in[5], (const float*)d_in[6], (const float*)d_in[7]};
    const float* Wg[3] = {(const float*)d_in[8], (const float*)d_in[9], (const float*)d_in[10]};
    const float* linW  = (const float*)d_in[11];
    const float* linb  = (const float*)d_in[12];
    float* out = (float*)d_out;
    int ne = in_sizes[1];

    float* h    = (float*)sym(g_h);
    float* z0   = (float*)sym(g_z0);
    float* bufA = (float*)sym(g_bufA);
    float* t1   = (float*)sym(g_t1);
    float* t2   = (float*)sym(g_t2);
    float* u1   = (float*)sym(g_u1);
    float* sig  = (float*)sym(g_sig);
    int* cnt    = (int*)sym(g_cnt);
    int* ptrR   = (int*)sym(g_ptrR);
    int* nextR  = (int*)sym(g_nextR);
    int* colR   = (int*)sym(g_colR);
    float* valR = (float*)sym(g_valR);
    int* ptrC   = (int*)sym(g_ptrC);
    int* nextC  = (int*)sym(g_nextC);
    int* colC   = (int*)sym(g_colC);
    float* valC = (float*)sym(g_valC);

    // output layout (tuple order, f32, concatenated)
    const size_t zoff[3] = {0ul, 17825792ul, 35651584ul};
    const size_t roff[3] = {1048576ul, 18874368ul, 36700160ul};
    const size_t lossoff = 53477376ul;
    const size_t predoff = 53477377ul;

    int neb = (ne + 255) / 256;

    // CSR by row
    zero_int_kernel<<<16, 256>>>(cnt, NN_);
    hist_kernel<<<neb, 256>>>(arows, cnt, ne);
    exscan_kernel<<<1, 1024>>>(cnt, ptrR, nextR);
    scatter_kernel<<<neb, 256>>>(arows, acols, avals, nextR, colR, valR, ne);
    // CSR by col (A^T)
    zero_int_kernel<<<16, 256>>>(cnt, NN_);
    hist_kernel<<<neb, 256>>>(acols, cnt, ne);
    exscan_kernel<<<1, 1024>>>(cnt, ptrC, nextC);
    scatter_kernel<<<neb, 256>>>(acols, arows, avals, nextC, colC, valC, ne);

    dim3 gS(HID_ / 64, NN_ / 64);  // (4, 64)  : 4096 x 256 outputs
    dim3 gB(NN_ / 64, NN_ / 64);   // (64, 64) : 4096 x 4096 outputs

    // h = relu(spmm(X @ Wsh))
    gemm64_kernel<false, 0><<<gS, 256>>>(X, Wsh, nullptr, bufA, NN_, HID_, FIN_);
    spmm_csr_kernel<<<NN_, HID_>>>(ptrR, colR, valR, bufA, h, 1);

    for (int b = 0; b < 3; b++) {
        float* zout = out + zoff[b];
        float* rout = out + roff[b];
        // z0 = relu(spmm(h @ Wb))
        gemm64_kernel<false, 0><<<gS, 256>>>(h, Wb[b], nullptr, bufA, NN_, HID_, HID_);
        spmm_csr_kernel<<<NN_, HID_>>>(ptrR, colR, valR, bufA, z0, 1);
        // sig = sigmoid(z0 @ z0^T)   (symmetric)
        gemm64_kernel<true, 2><<<gB, 256>>>(z0, z0, nullptr, sig, NN_, NN_, HID_);
        // hW = z0 @ Wg
        gemm64_kernel<false, 0><<<gS, 256>>>(z0, Wg[b], nullptr, bufA, NN_, HID_, HID_);
        // t1 = A^T @ hW
        spmm_csr_kernel<<<NN_, HID_>>>(ptrC, colC, valC, bufA, t1, 0);
        // t2 = sig @ hW   (== sig^T @ hW)
        gemm64_kernel<false, 0><<<gS, 256>>>(sig, bufA, nullptr, t2, NN_, HID_, NN_);
        // u1 = A @ t1
        spmm_csr_kernel<<<NN_, HID_>>>(ptrR, colR, valR, t1, u1, 0);
        // z = relu(sig @ t2 + u1)
        gemm64_kernel<false, 3><<<gS, 256>>>(sig, t2, u1, zout, NN_, HID_, NN_);
        // rec = z @ z^T
        gemm64_kernel<true, 0><<<gB, 256>>>(zout, zout, nullptr, rout, NN_, NN_, HID_);
    }

    pred_kernel<<<16, 256>>>(out + zoff[0], out + zoff[1], linW, linb, out + predoff);
    write_loss_kernel<<<1, 1>>>(out + lossoff);
}

// round 4
// speedup vs baseline: 2.8622x; 2.8622x over previous
#include <cuda_runtime.h>
#include <cstdint>

#define NN_ 4096
#define FIN_ 512
#define HID_ 256
#define NE_MAX 131072

// ---------------- scratch ----------------
__device__ float g_h[NN_ * HID_];
__device__ float g_z0[NN_ * HID_];
__device__ float g_bufA[NN_ * HID_];
__device__ float g_t1[NN_ * HID_];
__device__ float g_t2[NN_ * HID_];
__device__ float g_u1[NN_ * HID_];
__device__ float g_zr[NN_ * HID_];
__device__ float g_sig[(size_t)NN_ * NN_];
__device__ float g_Xr[NN_ * FIN_];
__device__ float g_Wr[FIN_ * HID_ + 6 * HID_ * HID_];
__device__ float g_part[4 * NN_ * HID_];

__device__ int   g_cnt[NN_];
__device__ int   g_ptrR[NN_ + 1];
__device__ int   g_nextR[NN_];
__device__ int   g_colR[NE_MAX];
__device__ float g_valR[NE_MAX];
__device__ int   g_ptrC[NN_ + 1];
__device__ int   g_nextC[NN_];
__device__ int   g_colC[NE_MAX];
__device__ float g_valC[NE_MAX];

// ---------------- helpers ----------------
__device__ __forceinline__ uint32_t smem_u32(const void* p) {
    uint32_t a;
    asm("{ .reg .u64 t; cvta.to.shared.u64 t, %1; cvt.u32.u64 %0, t; }" : "=r"(a) : "l"(p));
    return a;
}
__device__ __forceinline__ float rtf32(float x) {
    uint32_t u;
    asm("cvt.rna.tf32.f32 %0, %1;" : "=r"(u) : "f"(x));
    return __uint_as_float(u);
}
#define CP16(d, s) asm volatile("cp.async.ca.shared.global [%0], [%1], 16;" :: "r"(d), "l"(s))
#define CPCOMMIT() asm volatile("cp.async.commit_group;" ::: "memory")
#define CPWAIT0() asm volatile("cp.async.wait_group 0;" ::: "memory")

// ---------------- tf32 mma.sync GEMM ----------------
// C[.,Nc] = epi(A[M,K] @ op(B)).  TRB: B is [Nc,K] (A@B^T), else B is [K,Nc].
// EPI: 0 none, 2 sigmoid. SMODE: 0 plain, 1 rtf32 store, 2 plain->C + rtf32->C2.
// SYM: symmetric output, mirror store (tile list of 528).
static constexpr int SMEM_BYTES = (9216 + 2 * 4608) * 4;  // 73728

template <bool TRB, int EPI, bool SYM, int SMODE>
__global__ __launch_bounds__(256) void tcg(
    const float* __restrict__ A, const float* __restrict__ B,
    float* __restrict__ C, float* __restrict__ C2,
    int Nc, int K, int KCn, int tilesN, long long cstride) {
    extern __shared__ float sm[];
    const int tid = threadIdx.x, lane = tid & 31, wid = tid >> 5;
    const int wm = wid >> 2, wn = wid & 3;
    const int g = lane >> 2, t = lane & 3;

    int i, j;
    if (SYM) {
        int b = blockIdx.x, row = 0;
        while (b >= tilesN - row) { b -= tilesN - row; row++; }
        i = row; j = row + b;
    } else {
        i = blockIdx.x / tilesN; j = blockIdx.x % tilesN;
    }
    const int m0 = i * 128, n0 = j * 128;
    const int kb = blockIdx.y * KCn;
    C += (size_t)blockIdx.y * cstride;

    const uint32_t sbase = smem_u32(sm);
    const int BSTR = TRB ? 4608 : 4352;

    float acc[4][4][4];
    #pragma unroll
    for (int a = 0; a < 4; a++)
        #pragma unroll
        for (int b = 0; b < 4; b++)
            #pragma unroll
            for (int c = 0; c < 4; c++) acc[a][b][c] = 0.f;

    auto load_tile = [&](int akc, int buf) {
        {
            int r = tid >> 1, c0 = (tid & 1) * 16;
            const float* s = A + (size_t)(m0 + r) * K + akc * 32 + c0;
            uint32_t d = sbase + (uint32_t)((buf * 4608 + r * 36 + c0) * 4);
            #pragma unroll
            for (int q = 0; q < 4; q++) CP16(d + q * 16, s + q * 4);
        }
        if (TRB) {
            int r = tid >> 1, c0 = (tid & 1) * 16;
            const float* s = B + (size_t)(n0 + r) * K + akc * 32 + c0;
            uint32_t d = sbase + (uint32_t)((9216 + buf * 4608 + r * 36 + c0) * 4);
            #pragma unroll
            for (int q = 0; q < 4; q++) CP16(d + q * 16, s + q * 4);
        } else {
            int r = tid >> 3, c0 = (tid & 7) * 16;
            const float* s = B + (size_t)(akc * 32 + r) * Nc + n0 + c0;
            uint32_t d = sbase + (uint32_t)((9216 + buf * 4352 + r * 136 + c0) * 4);
            #pragma unroll
            for (int q = 0; q < 4; q++) CP16(d + q * 16, s + q * 4);
        }
    };

    load_tile(kb, 0);
    CPCOMMIT();
    int buf = 0;
    for (int c = 0; c < KCn; c++) {
        CPWAIT0();
        __syncthreads();
        if (c + 1 < KCn) { load_tile(kb + c + 1, buf ^ 1); CPCOMMIT(); }
        const uint32_t* As = (const uint32_t*)sm + buf * 4608;
        const uint32_t* Bs = (const uint32_t*)sm + 9216 + buf * BSTR;
        #pragma unroll
        for (int ks = 0; ks < 4; ks++) {
            const int k0 = ks * 8;
            uint32_t a[4][4];
            #pragma unroll
            for (int mf = 0; mf < 4; mf++) {
                const uint32_t* ap = As + (wm * 64 + mf * 16 + g) * 36 + k0 + t;
                a[mf][0] = ap[0];
                a[mf][1] = ap[8 * 36];
                a[mf][2] = ap[4];
                a[mf][3] = ap[8 * 36 + 4];
            }
            #pragma unroll
            for (int nf = 0; nf < 4; nf++) {
                uint32_t b0, b1;
                if (TRB) {
                    const uint32_t* bp = Bs + (wn * 32 + nf * 8 + g) * 36 + k0 + t;
                    b0 = bp[0]; b1 = bp[4];
                } else {
                    const uint32_t* bp = Bs + (k0 + t) * 136 + wn * 32 + nf * 8 + g;
                    b0 = bp[0]; b1 = bp[544];
                }
                #pragma unroll
                for (int mf = 0; mf < 4; mf++) {
                    asm volatile(
                        "mma.sync.aligned.m16n8k8.row.col.f32.tf32.tf32.f32 "
                        "{%0,%1,%2,%3}, {%4,%5,%6,%7}, {%8,%9}, {%0,%1,%2,%3};"
                        : "+f"(acc[mf][nf][0]), "+f"(acc[mf][nf][1]),
                          "+f"(acc[mf][nf][2]), "+f"(acc[mf][nf][3])
                        : "r"(a[mf][0]), "r"(a[mf][1]), "r"(a[mf][2]), "r"(a[mf][3]),
                          "r"(b0), "r"(b1));
                }
            }
        }
        __syncthreads();
        buf ^= 1;
    }

    // epilogue
    #pragma unroll
    for (int mf = 0; mf < 4; mf++) {
        int r0 = m0 + wm * 64 + mf * 16 + g;
        #pragma unroll
        for (int nf = 0; nf < 4; nf++) {
            int cc = n0 + wn * 32 + nf * 8 + 2 * t;
            float v[4];
            #pragma unroll
            for (int q = 0; q < 4; q++) {
                float x = acc[mf][nf][q];
                if (EPI == 2) x = 1.f / (1.f + __expf(-x));
                v[q] = x;
            }
            float w[4];
            #pragma unroll
            for (int q = 0; q < 4; q++) w[q] = (SMODE == 1) ? rtf32(v[q]) : v[q];
            *reinterpret_cast<float2*>(&C[(size_t)r0 * Nc + cc]) = make_float2(w[0], w[1]);
            *reinterpret_cast<float2*>(&C[(size_t)(r0 + 8) * Nc + cc]) = make_float2(w[2], w[3]);
            if (SMODE == 2) {
                *reinterpret_cast<float2*>(&C2[(size_t)r0 * Nc + cc]) =
                    make_float2(rtf32(v[0]), rtf32(v[1]));
                *reinterpret_cast<float2*>(&C2[(size_t)(r0 + 8) * Nc + cc]) =
                    make_float2(rtf32(v[2]), rtf32(v[3]));
            }
            if (SYM && i != j) {
                C[(size_t)cc * Nc + r0] = w[0];
                C[(size_t)(cc + 1) * Nc + r0] = w[1];
                C[(size_t)cc * Nc + r0 + 8] = w[2];
                C[(size_t)(cc + 1) * Nc + r0 + 8] = w[3];
            }
        }
    }
}

// ---------------- split-K reduce ----------------
__global__ void reduce4_round(const float* __restrict__ p, float* __restrict__ o) {
    int i = (blockIdx.x * blockDim.x + threadIdx.x) * 4;
    const int n = NN_ * HID_;
    float4 a = *reinterpret_cast<const float4*>(p + i);
    float4 b = *reinterpret_cast<const float4*>(p + n + i);
    float4 c = *reinterpret_cast<const float4*>(p + 2 * n + i);
    float4 d = *reinterpret_cast<const float4*>(p + 3 * n + i);
    float4 r;
    r.x = rtf32(a.x + b.x + c.x + d.x);
    r.y = rtf32(a.y + b.y + c.y + d.y);
    r.z = rtf32(a.z + b.z + c.z + d.z);
    r.w = rtf32(a.w + b.w + c.w + d.w);
    *reinterpret_cast<float4*>(o + i) = r;
}
__global__ void reduce4_addrelu(const float* __restrict__ p, const float* __restrict__ u,
                                float* __restrict__ z, float* __restrict__ zr) {
    int i = (blockIdx.x * blockDim.x + threadIdx.x) * 4;
    const int n = NN_ * HID_;
    float4 a = *reinterpret_cast<const float4*>(p + i);
    float4 b = *reinterpret_cast<const float4*>(p + n + i);
    float4 c = *reinterpret_cast<const float4*>(p + 2 * n + i);
    float4 d = *reinterpret_cast<const float4*>(p + 3 * n + i);
    float4 uu = *reinterpret_cast<const float4*>(u + i);
    float4 zz, rr;
    zz.x = fmaxf(a.x + b.x + c.x + d.x + uu.x, 0.f);
    zz.y = fmaxf(a.y + b.y + c.y + d.y + uu.y, 0.f);
    zz.z = fmaxf(a.z + b.z + c.z + d.z + uu.z, 0.f);
    zz.w = fmaxf(a.w + b.w + c.w + d.w + uu.w, 0.f);
    rr.x = rtf32(zz.x); rr.y = rtf32(zz.y); rr.z = rtf32(zz.z); rr.w = rtf32(zz.w);
    *reinterpret_cast<float4*>(z + i) = zz;
    *reinterpret_cast<float4*>(zr + i) = rr;
}

// ---------------- CSR build ----------------
__global__ void zero_int_kernel(int* p, int n) {
    int i = blockIdx.x * blockDim.x + threadIdx.x;
    if (i < n) p[i] = 0;
}
__global__ void hist_kernel(const int* __restrict__ k, int* __restrict__ c, int ne) {
    int i = blockIdx.x * blockDim.x + threadIdx.x;
    if (i < ne) atomicAdd(&c[k[i]], 1);
}
__global__ void exscan_kernel(const int* __restrict__ cnt, int* __restrict__ rp, int* __restrict__ nx) {
    __shared__ int sums[1024];
    int t = threadIdx.x;
    int v0 = cnt[t * 4], v1 = cnt[t * 4 + 1], v2 = cnt[t * 4 + 2], v3 = cnt[t * 4 + 3];
    sums[t] = v0 + v1 + v2 + v3;
    __syncthreads();
    for (int off = 1; off < 1024; off <<= 1) {
        int x = (t >= off) ? sums[t - off] : 0;
        __syncthreads();
        sums[t] += x;
        __syncthreads();
    }
    int run = (t > 0) ? sums[t - 1] : 0;
    rp[t * 4] = run; nx[t * 4] = run; run += v0;
    rp[t * 4 + 1] = run; nx[t * 4 + 1] = run; run += v1;
    rp[t * 4 + 2] = run; nx[t * 4 + 2] = run; run += v2;
    rp[t * 4 + 3] = run; nx[t * 4 + 3] = run; run += v3;
    if (t == 1023) rp[4096] = run;
}
__global__ void scatter_kernel(const int* __restrict__ k, const int* __restrict__ o,
                               const float* __restrict__ v, int* __restrict__ nx,
                               int* __restrict__ ec, float* __restrict__ ev, int ne) {
    int i = blockIdx.x * blockDim.x + threadIdx.x;
    if (i < ne) {
        int p = atomicAdd(&nx[k[i]], 1);
        ec[p] = o[i];
        ev[p] = v[i];
    }
}

// ---------------- SpMM ----------------
__global__ __launch_bounds__(HID_) void spmm_csr_kernel(
    const int* __restrict__ rowptr, const int* __restrict__ ecol,
    const float* __restrict__ eval, const float* __restrict__ in,
    float* __restrict__ out, int mode) {
    int r = blockIdx.x, f = threadIdx.x;
    int s = rowptr[r], e = rowptr[r + 1];
    __shared__ int   scol[HID_];
    __shared__ float sval[HID_];
    float acc = 0.f;
    for (int base = s; base < e; base += HID_) {
        int n = e - base;
        if (n > HID_) n = HID_;
        if (f < n) { scol[f] = ecol[base + f]; sval[f] = eval[base + f]; }
        __syncthreads();
        #pragma unroll 4
        for (int i = 0; i < n; i++) acc += sval[i] * in[scol[i] * HID_ + f];
        __syncthreads();
    }
    if (mode >= 1) acc = fmaxf(acc, 0.f);
    if (mode == 2) acc = rtf32(acc);
    out[r * HID_ + f] = acc;
}

// ---------------- prep / head ----------------
__global__ void round_copy_kernel(const float* __restrict__ x, float* __restrict__ y, int n) {
    int i = blockIdx.x * blockDim.x + threadIdx.x;
    if (i < n) y[i] = rtf32(x[i]);
}
__global__ void pred_kernel(const float* __restrict__ z_iv, const float* __restrict__ z_c,
                            const float* __restrict__ linW, const float* __restrict__ linb,
                            float* __restrict__ out) {
    int i = blockIdx.x * blockDim.x + threadIdx.x;
    if (i >= NN_) return;
    float l0 = linb[0], l1 = linb[1];
    #pragma unroll 4
    for (int k = 0; k < HID_; k++) {
        float v = z_iv[i * HID_ + k];
        l0 += v * linW[k * 2];
        l1 += v * linW[k * 2 + 1];
    }
    #pragma unroll 4
    for (int k = 0; k < HID_; k++) {
        float v = z_c[i * HID_ + k];
        l0 += v * linW[(HID_ + k) * 2];
        l1 += v * linW[(HID_ + k) * 2 + 1];
    }
    float m = fmaxf(l0, l1);
    float lse = m + logf(expf(l0 - m) + expf(l1 - m));
    out[i * 2] = l0 - lse;
    out[i * 2 + 1] = l1 - lse;
}
__global__ void write_loss_kernel(float* p) { *p = 0.f; }

// ---------------- host ----------------
static void* sym(const void* s) { void* p = nullptr; cudaGetSymbolAddress(&p, s); return p; }

extern "C" void kernel_launch(void* const* d_in, const int* in_sizes, int n_in,
                              void* d_out, int out_size) {
    const float* X     = (const float*)d_in[0];
    const int*   arows = (const int*)d_in[1];
    const int*   acols = (const int*)d_in[2];
    const float* avals = (const float*)d_in[3];
    const float* Wsh   = (const float*)d_in[4];
    const float* Wb[3] = {(const float*)d_in[5], (const float*)d_in[6], (const float*)d_in[7]};
    const float* Wg[3] = {(const float*)d_in[8], (const float*)d_in[9], (const float*)d_in[10]};
    const float* linW  = (const float*)d_in[11];
    const float* linb  = (const float*)d_in[12];
    float* out = (float*)d_out;
    int ne = in_sizes[1];

    float* h    = (float*)sym(g_h);
    float* z0   = (float*)sym(g_z0);
    float* bufA = (float*)sym(g_bufA);
    float* t1   = (float*)sym(g_t1);
    float* t2   = (float*)sym(g_t2);
    float* u1   = (float*)sym(g_u1);
    float* zr   = (float*)sym(g_zr);
    float* sig  = (float*)sym(g_sig);
    float* Xr   = (float*)sym(g_Xr);
    float* Wr   = (float*)sym(g_Wr);
    float* part = (float*)sym(g_part);
    int* cnt = (int*)sym(g_cnt);
    int* ptrR = (int*)sym(g_ptrR); int* nextR = (int*)sym(g_nextR);
    int* colR = (int*)sym(g_colR); float* valR = (float*)sym(g_valR);
    int* ptrC = (int*)sym(g_ptrC); int* nextC = (int*)sym(g_nextC);
    int* colC = (int*)sym(g_colC); float* valC = (float*)sym(g_valC);

    cudaFuncSetAttribute(tcg<false, 0, false, 0>, cudaFuncAttributeMaxDynamicSharedMemorySize, SMEM_BYTES);
    cudaFuncSetAttribute(tcg<false, 0, false, 1>, cudaFuncAttributeMaxDynamicSharedMemorySize, SMEM_BYTES);
    cudaFuncSetAttribute(tcg<true, 2, true, 1>, cudaFuncAttributeMaxDynamicSharedMemorySize, SMEM_BYTES);
    cudaFuncSetAttribute(tcg<true, 0, true, 0>, cudaFuncAttributeMaxDynamicSharedMemorySize, SMEM_BYTES);

    const size_t zoff[3] = {0ul, 17825792ul, 35651584ul};
    const size_t roff[3] = {1048576ul, 18874368ul, 36700160ul};
    const size_t lossoff = 53477376ul, predoff = 53477377ul;

    int neb = (ne + 255) / 256;

    // rounded operand copies
    round_copy_kernel<<<(NN_ * FIN_ + 255) / 256, 256>>>(X, Xr, NN_ * FIN_);
    round_copy_kernel<<<(FIN_ * HID_ + 255) / 256, 256>>>(Wsh, Wr, FIN_ * HID_);
    for (int b = 0; b < 3; b++) {
        round_copy_kernel<<<256, 256>>>(Wb[b], Wr + FIN_ * HID_ + b * 65536, HID_ * HID_);
        round_copy_kernel<<<256, 256>>>(Wg[b], Wr + FIN_ * HID_ + (3 + b) * 65536, HID_ * HID_);
    }

    // CSR by row and by col
    zero_int_kernel<<<16, 256>>>(cnt, NN_);
    hist_kernel<<<neb, 256>>>(arows, cnt, ne);
    exscan_kernel<<<1, 1024>>>(cnt, ptrR, nextR);
    scatter_kernel<<<neb, 256>>>(arows, acols, avals, nextR, colR, valR, ne);
    zero_int_kernel<<<16, 256>>>(cnt, NN_);
    hist_kernel<<<neb, 256>>>(acols, cnt, ne);
    exscan_kernel<<<1, 1024>>>(cnt, ptrC, nextC);
    scatter_kernel<<<neb, 256>>>(acols, arows, avals, nextC, colC, valC, ne);

    // h = rtf32(relu(spmm(Xr @ Wsh)))
    tcg<false, 0, false, 0><<<64, 256, SMEM_BYTES>>>(Xr, Wr, bufA, nullptr, 256, 512, 16, 2, 0);
    spmm_csr_kernel<<<NN_, HID_>>>(ptrR, colR, valR, bufA, h, 2);

    for (int b = 0; b < 3; b++) {
        float* zout = out + zoff[b];
        float* rout = out + roff[b];
        const float* Wbb = Wr + FIN_ * HID_ + b * 65536;
        const float* Wgb = Wr + FIN_ * HID_ + (3 + b) * 65536;
        // z0 = rtf32(relu(spmm(h @ Wb)))
        tcg<false, 0, false, 0><<<64, 256, SMEM_BYTES>>>(h, Wbb, bufA, nullptr, 256, 256, 8, 2, 0);
        spmm_csr_kernel<<<NN_, HID_>>>(ptrR, colR, valR, bufA, z0, 2);
        // sig = rtf32(sigmoid(z0 @ z0^T))  [symmetric]
        tcg<true, 2, true, 1><<<528, 256, SMEM_BYTES>>>(z0, z0, sig, nullptr, 4096, 256, 8, 32, 0);
        // hW = rtf32(z0 @ Wg)
        tcg<false, 0, false, 1><<<64, 256, SMEM_BYTES>>>(z0, Wgb, bufA, nullptr, 256, 256, 8, 2, 0);
        // t1 = A^T @ hW
        spmm_csr_kernel<<<NN_, HID_>>>(ptrC, colC, valC, bufA, t1, 0);
        // t2 = rtf32(sig @ hW)  [split-K x4]
        tcg<false, 0, false, 0><<<dim3(64, 4), 256, SMEM_BYTES>>>(sig, bufA, part, nullptr, 256, 4096, 32, 2, (long long)NN_ * HID_);
        reduce4_round<<<1024, 256>>>(part, t2);
        // u1 = A @ t1
        spmm_csr_kernel<<<NN_, HID_>>>(ptrR, colR, valR, t1, u1, 0);
        // z = relu(sig @ t2 + u1)  [split-K x4; fp32->zout, rtf32->zr]
        tcg<false, 0, false, 0><<<dim3(64, 4), 256, SMEM_BYTES>>>(sig, t2, part, nullptr, 256, 4096, 32, 2, (long long)NN_ * HID_);
        reduce4_addrelu<<<1024, 256>>>(part, u1, zout, zr);
        // rec = zr @ zr^T  [symmetric]
        tcg<true, 0, true, 0><<<528, 256, SMEM_BYTES>>>(zr, zr, rout, nullptr, 4096, 256, 8, 32, 0);
    }

    pred_kernel<<<16, 256>>>(out + zoff[0], out + zoff[1], linW, linb, out + predoff);
    write_loss_kernel<<<1, 1>>>(out + lossoff);
}